// round 10
// baseline (speedup 1.0000x reference)
#include <cuda_runtime.h>
#include <stdint.h>

// Problem constants
#define NB   8
#define CIN  3
#define HW   128
#define OC   16
#define NF   27

// cin=0 taps (f 0-8): SMEM split half-tables, 16B rows (8 channels each)
__device__ __align__(16) short g_prodA[9*256*8];    // 36KB ch0-7
__device__ __align__(16) short g_prodB[9*256*8];    // 36KB ch8-15
// cin=1,2 taps (f 9-26): L2-resident table, 32B rows (16 channels)
__device__ __align__(32) short g_prodL[18*256*16];  // 144KB

// ---------------------------------------------------------------------------
// Table builder: one thread per (f, ip, o).
// ---------------------------------------------------------------------------
__global__ void prep_table(const float* __restrict__ w,
                           const float* __restrict__ swp,
                           const int*   __restrict__ lut)
{
    int idx = blockIdx.x * blockDim.x + threadIdx.x;   // 110592
    if (idx >= NF*256*OC) return;
    int o  = idx & 15;
    int ip = (idx >> 4) & 255;
    int f  = idx >> 12;

    float q = rintf(w[o*NF + f] / swp[0]);   // round-half-even like jnp.round
    q = fminf(fmaxf(q, -127.0f), 127.0f);
    int iw = (int)q + 128;

    int row = ip*256 + iw;
    int2 hl = ((const int2*)lut)[row];
    short v = (short)(hl.x*256 + (hl.y & 255));

    if (f < 9) {
        if (o < 8) g_prodA[(f*256 + ip)*8 + o]     = v;
        else       g_prodB[(f*256 + ip)*8 + (o-8)] = v;
    } else {
        g_prodL[((f-9)*256 + ip)*16 + o] = v;
    }
}

// ---------------------------------------------------------------------------
// Conv: 128 blocks x 1024 threads, 1 thread/pixel.
// cin0 taps from SMEM (72KB tables), cin1/2 taps gathered from L2 (__ldcg),
// 2-tap-deep LDG register pipeline. Two hardware paths run concurrently.
// ---------------------------------------------------------------------------
#define SM_A_BYTES    (9*256*8*2)               // 36864
#define SM_AB_BYTES   (2*SM_A_BYTES)            // 73728
#define SM_TILE_BYTES ((3*10*130 + 15) & ~15)   // 3904
#define SM_TOTAL      (SM_AB_BYTES + SM_TILE_BYTES)

#define TOFF(f) (((f)/9)*1300 + (((f)%9)/3)*130 + ((f)%3))

#define ACC16(va, vb)                                   \
    acc[ 0] = __dp2a_lo((int)(va).x, 0x0001, acc[ 0]);  \
    acc[ 1] = __dp2a_lo((int)(va).x, 0x0100, acc[ 1]);  \
    acc[ 2] = __dp2a_lo((int)(va).y, 0x0001, acc[ 2]);  \
    acc[ 3] = __dp2a_lo((int)(va).y, 0x0100, acc[ 3]);  \
    acc[ 4] = __dp2a_lo((int)(va).z, 0x0001, acc[ 4]);  \
    acc[ 5] = __dp2a_lo((int)(va).z, 0x0100, acc[ 5]);  \
    acc[ 6] = __dp2a_lo((int)(va).w, 0x0001, acc[ 6]);  \
    acc[ 7] = __dp2a_lo((int)(va).w, 0x0100, acc[ 7]);  \
    acc[ 8] = __dp2a_lo((int)(vb).x, 0x0001, acc[ 8]);  \
    acc[ 9] = __dp2a_lo((int)(vb).x, 0x0100, acc[ 9]);  \
    acc[10] = __dp2a_lo((int)(vb).y, 0x0001, acc[10]);  \
    acc[11] = __dp2a_lo((int)(vb).y, 0x0100, acc[11]);  \
    acc[12] = __dp2a_lo((int)(vb).z, 0x0001, acc[12]);  \
    acc[13] = __dp2a_lo((int)(vb).z, 0x0100, acc[13]);  \
    acc[14] = __dp2a_lo((int)(vb).w, 0x0001, acc[14]);  \
    acc[15] = __dp2a_lo((int)(vb).w, 0x0100, acc[15]);

__global__ __launch_bounds__(1024, 1)
void conv_kernel(const float* __restrict__ x,
                 const float* __restrict__ bias,
                 const float* __restrict__ sxp,
                 const float* __restrict__ swp,
                 float* __restrict__ out)
{
    extern __shared__ char smem[];
    unsigned char* stile = (unsigned char*)(smem + SM_AB_BYTES);

    const int tid  = threadIdx.x;
    const int b    = blockIdx.x >> 4;
    const int rowg = blockIdx.x & 15;

    // Stage cin0 half-tables (72KB)
    {
        const int4* srcA = (const int4*)g_prodA;
        const int4* srcB = (const int4*)g_prodB;
        int4* dstA = (int4*)smem;
        int4* dstB = (int4*)(smem + SM_A_BYTES);
        #pragma unroll
        for (int k = 0; k < 2; k++) {
            dstA[tid + k*1024] = srcA[tid + k*1024];
            dstB[tid + k*1024] = srcB[tid + k*1024];
        }
        if (tid < (SM_A_BYTES/16 - 2048)) {   // 2304 - 2048 = 256
            dstA[tid + 2048] = srcA[tid + 2048];
            dstB[tid + 2048] = srcB[tid + 2048];
        }
    }

    // Stage + quantize activation tile [3][10][130]; out-of-image -> ip=128
    {
        const float sx = sxp[0];
        for (int t = tid; t < 3*10*130; t += 1024) {
            int cin = t / 1300;
            int rem = t - cin*1300;
            int rr  = rem / 130;
            int cc  = rem - rr*130;
            int hh  = rowg*8 + rr - 1;
            int ww  = cc - 1;
            unsigned char v = 128;
            if ((unsigned)hh < 128u && (unsigned)ww < 128u) {
                float xf = x[((b*3 + cin)*128 + hh)*128 + ww];
                float q = rintf(xf / sx);
                q = fminf(fmaxf(q, -127.0f), 127.0f);
                v = (unsigned char)((int)q + 128);
            }
            stile[t] = v;
        }
    }
    __syncthreads();

    const int c = tid & 127;
    const int r = tid >> 7;

    int acc[OC];
    #pragma unroll
    for (int o = 0; o < OC; o++) acc[o] = 0;

    const uint4* TA = (const uint4*)smem;
    const uint4* TB = (const uint4*)(smem + SM_A_BYTES);
    const uint4* L  = (const uint4*)g_prodL;
    const unsigned char* tb = &stile[r*130 + c];

    // Prime the 2-deep LDG pipeline with L2 taps t=0,1 (f=9,10)
    uint4 a0, b0, a1, b1;
    {
        int ip0 = (int)tb[TOFF(9)];
        int ip1 = (int)tb[TOFF(10)];
        a0 = __ldcg(&L[(0*256 + ip0)*2]);
        b0 = __ldcg(&L[(0*256 + ip0)*2 + 1]);
        a1 = __ldcg(&L[(1*256 + ip1)*2]);
        b1 = __ldcg(&L[(1*256 + ip1)*2 + 1]);
    }

    #pragma unroll
    for (int t = 0; t < 18; t++) {
        // Grab the L2 tap loaded 2 iterations ago
        uint4 va = (t & 1) ? a1 : a0;
        uint4 vb = (t & 1) ? b1 : b0;

        // Refill this slot with L2 tap t+2 (f = t+11)
        if (t + 2 < 18) {
            int ipn = (int)tb[TOFF(t + 11)];
            if (t & 1) {
                a1 = __ldcg(&L[((t+2)*256 + ipn)*2]);
                b1 = __ldcg(&L[((t+2)*256 + ipn)*2 + 1]);
            } else {
                a0 = __ldcg(&L[((t+2)*256 + ipn)*2]);
                b0 = __ldcg(&L[((t+2)*256 + ipn)*2 + 1]);
            }
        }

        // Interleave one SMEM tap on even iterations (9 taps total, f=0..8)
        if ((t & 1) == 0) {
            int f  = t >> 1;
            int ips = (int)tb[TOFF(f)];
            uint4 sa = TA[f*256 + ips];
            uint4 sb = TB[f*256 + ips];
            ACC16(sa, sb)
        }

        ACC16(va, vb)

        asm volatile("" ::: "memory");   // bound instruction motion per tap
    }

    const float s = sxp[0] * swp[0];
    const int h = rowg*8 + r;
    float* obase = &out[(b*OC*128 + h)*128 + c];
    #pragma unroll
    for (int o = 0; o < OC; o++)
        obase[o*128*128] = (float)acc[o] * s + __ldg(&bias[o]);
}

// ---------------------------------------------------------------------------
extern "C" void kernel_launch(void* const* d_in, const int* in_sizes, int n_in,
                              void* d_out, int out_size)
{
    const float* x    = (const float*)d_in[0];
    const float* w    = (const float*)d_in[1];
    const float* bias = (const float*)d_in[2];
    const float* sx   = (const float*)d_in[3];
    const float* sw   = (const float*)d_in[4];
    const int*   lut  = (const int*)d_in[5];
    float* out = (float*)d_out;

    cudaFuncSetAttribute(conv_kernel,
                         cudaFuncAttributeMaxDynamicSharedMemorySize, SM_TOTAL);

    prep_table<<<(NF*256*OC + 255) / 256, 256>>>(w, sw, lut);
    conv_kernel<<<NB * 16, 1024, SM_TOTAL>>>(x, bias, sx, sw, out);
}

// round 11
// speedup vs baseline: 2.1110x; 2.1110x over previous
#include <cuda_runtime.h>
#include <stdint.h>

// Problem constants
#define NB   8
#define CIN  3
#define HW   128
#define OC   16
#define NF   27

// Device scratch: two half-tables, 16B rows (8 channels each).
__device__ __align__(16) short g_prodA[NF*256*8];   // [f][ip][o:0-7]   108KB
__device__ __align__(16) short g_prodB[NF*256*8];   // [f][ip][o:8-15]  108KB
__device__ int g_ctr;                               // work-stealing counter

// ---------------------------------------------------------------------------
// Table builder: one thread per (f, ip, o). Also resets the work counter.
// ---------------------------------------------------------------------------
__global__ void prep_table(const float* __restrict__ w,
                           const float* __restrict__ swp,
                           const int*   __restrict__ lut)
{
    int idx = blockIdx.x * blockDim.x + threadIdx.x;   // 110592
    if (idx == 0) g_ctr = 0;
    if (idx >= NF*256*OC) return;
    int o  = idx & 15;
    int ip = (idx >> 4) & 255;
    int f  = idx >> 12;

    float q = rintf(w[o*NF + f] / swp[0]);   // round-half-even like jnp.round
    q = fminf(fmaxf(q, -127.0f), 127.0f);
    int iw = (int)q + 128;

    int row = ip*256 + iw;
    int2 hl = ((const int2*)lut)[row];       // (hi, lo)
    short v = (short)(hl.x*256 + (hl.y & 255));

    if (o < 8) g_prodA[(f*256 + ip)*8 + o]     = v;
    else       g_prodB[(f*256 + ip)*8 + (o-8)] = v;
}

// ---------------------------------------------------------------------------
// Conv: 148 persistent blocks (one per SM), both half-tables in SMEM (216KB).
// Each block steals 512-pixel units (4 image rows) from a global counter:
// 256 units total -> time-balanced across all 148 SMs.
// Threads: tid>>9 selects channel half; each thread = 1 px x 8 ch.
// ---------------------------------------------------------------------------
#define SM_A_BYTES    (NF*256*8*2)              // 110592
#define SM_AB_BYTES   (2*SM_A_BYTES)            // 221184
#define TILE_ELEMS    (3*6*130)                 // 2340 (4 rows + halo)
#define SM_TILE_OFF   SM_AB_BYTES
#define SM_U_OFF      (SM_AB_BYTES + ((TILE_ELEMS + 15) & ~15))   // +2352
#define SM_TOTAL      (SM_U_OFF + 16)
#define NUM_UNITS     256                       // 8 batches x 32 row-chunks
#define GRID_CONV     148

__global__ __launch_bounds__(1024, 1)
void conv_kernel(const float* __restrict__ x,
                 const float* __restrict__ bias,
                 const float* __restrict__ sxp,
                 const float* __restrict__ swp,
                 float* __restrict__ out)
{
    extern __shared__ char smem[];
    unsigned char* stile = (unsigned char*)(smem + SM_TILE_OFF);
    int*           s_u   = (int*)(smem + SM_U_OFF);

    const int tid = threadIdx.x;

    // Stage both half-tables (216KB) once per block
    {
        const int4* srcA = (const int4*)g_prodA;
        const int4* srcB = (const int4*)g_prodB;
        int4* dstA = (int4*)smem;
        int4* dstB = (int4*)(smem + SM_A_BYTES);
        #pragma unroll
        for (int k = 0; k < 6; k++) {
            dstA[tid + k*1024] = srcA[tid + k*1024];
            dstB[tid + k*1024] = srcB[tid + k*1024];
        }
        if (tid < (SM_A_BYTES/16 - 6*1024)) {           // 768 remaining
            dstA[tid + 6*1024] = srcA[tid + 6*1024];
            dstB[tid + 6*1024] = srcB[tid + 6*1024];
        }
    }

    const int half = tid >> 9;          // 0: ch0-7, 1: ch8-15
    const int px   = tid & 511;
    const int r    = px >> 7;           // 0..3 row within unit
    const int c    = px & 127;          // column
    const float sx = sxp[0];
    const float s  = sxp[0] * swp[0];
    const uint4* T = (const uint4*)(smem + half*SM_A_BYTES);

    for (;;) {
        if (tid == 0) s_u[0] = atomicAdd(&g_ctr, 1);
        __syncthreads();                 // bcast unit id; also fences prior unit's reads
        const int u = s_u[0];
        if (u >= NUM_UNITS) break;

        const int b    = u >> 5;         // batch
        const int row0 = (u & 31) << 2;  // first of 4 image rows

        // Stage + quantize tile [3][6][130] for this unit; OOB -> ip=128
        for (int t = tid; t < TILE_ELEMS; t += 1024) {
            int cin = t / 780;
            int rem = t - cin*780;
            int rr  = rem / 130;
            int cc  = rem - rr*130;
            int hh  = row0 + rr - 1;
            int ww  = cc - 1;
            unsigned char v = 128;
            if ((unsigned)hh < 128u && (unsigned)ww < 128u) {
                float xf = x[((b*3 + cin)*128 + hh)*128 + ww];
                float q = rintf(xf / sx);                // round-half-even
                q = fminf(fmaxf(q, -127.0f), 127.0f);
                v = (unsigned char)((int)q + 128);
            }
            stile[t] = v;
        }
        __syncthreads();

        int acc[8];
        #pragma unroll
        for (int o = 0; o < 8; o++) acc[o] = 0;

        const unsigned char* tb = &stile[r*130 + c];

        #pragma unroll 1
        for (int cin = 0; cin < 3; cin++) {
            // Load the 9 tile bytes for this input channel (independent LDS)
            int ipx[9];
            #pragma unroll
            for (int dh = 0; dh < 3; dh++)
                #pragma unroll
                for (int dw = 0; dw < 3; dw++)
                    ipx[dh*3 + dw] = (int)tb[cin*780 + dh*130 + dw];

            // 9 straight-line taps: 1 LDS.128 + 8 dp2a each
            #pragma unroll
            for (int t = 0; t < 9; t++) {
                uint4 v = T[(cin*9 + t)*256 + ipx[t]];
                acc[0] = __dp2a_lo((int)v.x, 0x0001, acc[0]);
                acc[1] = __dp2a_lo((int)v.x, 0x0100, acc[1]);
                acc[2] = __dp2a_lo((int)v.y, 0x0001, acc[2]);
                acc[3] = __dp2a_lo((int)v.y, 0x0100, acc[3]);
                acc[4] = __dp2a_lo((int)v.z, 0x0001, acc[4]);
                acc[5] = __dp2a_lo((int)v.z, 0x0100, acc[5]);
                acc[6] = __dp2a_lo((int)v.w, 0x0001, acc[6]);
                acc[7] = __dp2a_lo((int)v.w, 0x0100, acc[7]);
            }
        }

        const int h = row0 + r;
        float* obase = &out[((b*OC + half*8)*128 + h)*128 + c];
        #pragma unroll
        for (int o = 0; o < 8; o++)
            obase[o*128*128] = (float)acc[o] * s + __ldg(&bias[half*8 + o]);
    }
}

// ---------------------------------------------------------------------------
extern "C" void kernel_launch(void* const* d_in, const int* in_sizes, int n_in,
                              void* d_out, int out_size)
{
    const float* x    = (const float*)d_in[0];
    const float* w    = (const float*)d_in[1];
    const float* bias = (const float*)d_in[2];
    const float* sx   = (const float*)d_in[3];
    const float* sw   = (const float*)d_in[4];
    const int*   lut  = (const int*)d_in[5];
    float* out = (float*)d_out;

    cudaFuncSetAttribute(conv_kernel,
                         cudaFuncAttributeMaxDynamicSharedMemorySize, SM_TOTAL);

    prep_table<<<(NF*256*OC + 255) / 256, 256>>>(w, sw, lut);
    conv_kernel<<<GRID_CONV, 1024, SM_TOTAL>>>(x, bias, sx, sw, out);
}

// round 12
// speedup vs baseline: 2.5957x; 1.2296x over previous
#include <cuda_runtime.h>
#include <stdint.h>

// Problem constants
#define NB   8
#define HW   128
#define OC   16
#define NF   27
#define NROWS_TOT 1024        // NB*HW global output rows
#define GRID_CONV 148

// Unified table: [f][ip][o] int16, 32B rows. Both 16B halves of a row share
// one 128B line -> 2-lane pixel pairing halves distinct-lines per LDS.128.
__device__ __align__(16) short g_prod[NF*256*OC];   // 216KB

// ---------------------------------------------------------------------------
// Table builder: one thread per (f, ip, o).
// ---------------------------------------------------------------------------
__global__ void prep_table(const float* __restrict__ w,
                           const float* __restrict__ swp,
                           const int*   __restrict__ lut)
{
    int idx = blockIdx.x * blockDim.x + threadIdx.x;   // 110592
    if (idx >= NF*256*OC) return;
    int o  = idx & 15;
    int ip = (idx >> 4) & 255;
    int f  = idx >> 12;

    float q = rintf(w[o*NF + f] / swp[0]);   // round-half-even like jnp.round
    q = fminf(fmaxf(q, -127.0f), 127.0f);
    int iw = (int)q + 128;

    int2 hl = ((const int2*)lut)[ip*256 + iw];   // (hi, lo)
    g_prod[(f*256 + ip)*16 + o] = (short)(hl.x*256 + (hl.y & 255));
}

// ---------------------------------------------------------------------------
// Conv: 148 blocks (one per SM), each owns a contiguous range of 6-7 global
// rows (statically balanced). Thread = (pixel, channel-half): 2 lanes share
// each pixel's 32B table row -> line-shared gathers.
// 4-slot circular register buffer over the flat 27-tap loop (R9-proven).
// ---------------------------------------------------------------------------
#define SM_T_BYTES  (NF*256*OC*2)     // 221184
#define TILE_STRIDE 1170              // 9 rows x 130 cols (max TR = 9)
#define SM_TOTAL    (SM_T_BYTES + 3*TILE_STRIDE + 16)   // 224710

__device__ __forceinline__ int tap_byte(const unsigned char* tb, int f,
                                        bool vT, bool vB)
{
    // f compile-time after unroll: offsets fold to immediates
    int cin = f / 9, dh = (f % 9) / 3, dw = f % 3;
    int v = (int)tb[cin*TILE_STRIDE + dh*130 + dw];
    if (dh == 0) v = vT ? v : 128;    // top image boundary -> pad
    if (dh == 2) v = vB ? v : 128;    // bottom image boundary -> pad
    return v;
}

__global__ __launch_bounds__(1024, 1)
void conv_kernel(const float* __restrict__ x,
                 const float* __restrict__ bias,
                 const float* __restrict__ sxp,
                 const float* __restrict__ swp,
                 float* __restrict__ out)
{
    extern __shared__ char smem[];
    unsigned char* stile = (unsigned char*)(smem + SM_T_BYTES);

    const int tid = threadIdx.x;
    const int bid = blockIdx.x;

    // Balanced contiguous global-row range [s, e)
    const int s  = (bid * NROWS_TOT) / GRID_CONV;
    const int e  = ((bid + 1) * NROWS_TOT) / GRID_CONV;
    const int TR = e - s + 2;                    // tile rows incl. halo (8 or 9)

    // Stage the 216KB table
    {
        const int4* src = (const int4*)g_prod;
        int4* dst = (int4*)smem;
        for (int i = tid; i < SM_T_BYTES/16; i += 1024)
            dst[i] = src[i];
    }

    // Stage + quantize tile [3][TR][130]; tile row t <-> global row s-1+t.
    // Out-of-tensor -> 128; image-boundary semantics handled at compute time.
    {
        const float sx = sxp[0];
        #pragma unroll 1
        for (int cin = 0; cin < 3; cin++) {
            for (int t = tid; t < TR*130; t += 1024) {
                int rr = t / 130;
                int cc = t - rr*130;
                int g  = s - 1 + rr;             // global row of this tile row
                int ww = cc - 1;
                unsigned char v = 128;
                if ((unsigned)g < 1024u && (unsigned)ww < 128u) {
                    int b = g >> 7, h = g & 127;
                    float xf = x[((b*3 + cin)*128 + h)*128 + ww];
                    float q = rintf(xf / sx);    // round-half-even
                    q = fminf(fmaxf(q, -127.0f), 127.0f);
                    v = (unsigned char)((int)q + 128);
                }
                stile[cin*TILE_STRIDE + t] = v;
            }
        }
    }
    __syncthreads();

    const int   hf = tid & 1;                    // channel half: 0 -> 0-7, 1 -> 8-15
    const float sc = sxp[0] * swp[0];
    const uint4* T = (const uint4*)smem;         // 2 uint4 per 32B row
    const int   P  = (e - s) * 128;              // pixels in this block's range

    #pragma unroll 1
    for (int pp = tid >> 1; pp < P; pp += 512) {
        const int rl = pp >> 7;                  // local row
        const int c  = pp & 127;                 // column
        const int r  = s + rl;                   // global row
        const int h  = r & 127;
        const int b  = r >> 7;
        const bool vT = (h != 0);                // warp-uniform predicates
        const bool vB = (h != 127);
        const unsigned char* tb = &stile[rl*130 + c];

        int acc[8];
        #pragma unroll
        for (int o = 0; o < 8; o++) acc[o] = 0;

        // Prime 4-deep circular buffer (4 LDS.128 in flight per warp)
        uint4 buf[4];
        #pragma unroll
        for (int j = 0; j < 4; j++) {
            int ip = tap_byte(tb, j, vT, vB);
            buf[j] = T[(j*256 + ip)*2 + hf];
        }

        #pragma unroll
        for (int f = 0; f < 27; f++) {
            uint4 v = buf[f & 3];
            if (f + 4 < 27) {                    // refill slot with tap f+4
                int ipn = tap_byte(tb, f + 4, vT, vB);
                buf[f & 3] = T[((f + 4)*256 + ipn)*2 + hf];
            }
            acc[0] = __dp2a_lo((int)v.x, 0x0001, acc[0]);
            acc[1] = __dp2a_lo((int)v.x, 0x0100, acc[1]);
            acc[2] = __dp2a_lo((int)v.y, 0x0001, acc[2]);
            acc[3] = __dp2a_lo((int)v.y, 0x0100, acc[3]);
            acc[4] = __dp2a_lo((int)v.z, 0x0001, acc[4]);
            acc[5] = __dp2a_lo((int)v.z, 0x0100, acc[5]);
            acc[6] = __dp2a_lo((int)v.w, 0x0001, acc[6]);
            acc[7] = __dp2a_lo((int)v.w, 0x0100, acc[7]);
            asm volatile("" ::: "memory");       // bound motion: 4-tap window
        }

        float* ob = &out[((b*OC + hf*8)*128 + h)*128 + c];
        #pragma unroll
        for (int o = 0; o < 8; o++)
            ob[o*128*128] = (float)acc[o] * sc + __ldg(&bias[hf*8 + o]);
    }
}

// ---------------------------------------------------------------------------
extern "C" void kernel_launch(void* const* d_in, const int* in_sizes, int n_in,
                              void* d_out, int out_size)
{
    const float* x    = (const float*)d_in[0];
    const float* w    = (const float*)d_in[1];
    const float* bias = (const float*)d_in[2];
    const float* sx   = (const float*)d_in[3];
    const float* sw   = (const float*)d_in[4];
    const int*   lut  = (const int*)d_in[5];
    float* out = (float*)d_out;

    cudaFuncSetAttribute(conv_kernel,
                         cudaFuncAttributeMaxDynamicSharedMemorySize, SM_TOTAL);

    prep_table<<<(NF*256*OC + 255) / 256, 256>>>(w, sw, lut);
    conv_kernel<<<GRID_CONV, 1024, SM_TOTAL>>>(x, bias, sx, sw, out);
}